// round 10
// baseline (speedup 1.0000x reference)
#include <cuda_runtime.h>

#define BATCH  32
#define SEQ    2048
#define CHUNK  512
#define NCHUNK 4                  // SEQ / CHUNK
#define NBLK   (BATCH * NCHUNK)   // 128
#define NTHR   256

// ---- scratch (allocation-free __device__ globals; counters monotone across replays) ----
__device__ float        g_sorted[BATCH * SEQ];
__device__ float        g_pcnt[NBLK], g_pdmz[NBLK], g_pdi[NBLK], g_pspm[NBLK],
                        g_pspi[NBLK], g_pmxm[NBLK], g_pmxi[NBLK], g_pint[NBLK];
__device__ unsigned int g_arrive[BATCH];   // per-batch sort-done tickets
__device__ unsigned int g_done;            // global finalize ticket

__device__ __forceinline__ int SK(int i) { return i + (i >> 5); }  // bank-skew index
#define REGZ  528                 // skewed size of one 512-chunk region
#define SKSZ  (NCHUNK * REGZ)     // 2112 floats

__device__ __forceinline__ float warpSum(float v) {
    #pragma unroll
    for (int o = 16; o; o >>= 1) v += __shfl_down_sync(0xffffffffu, v, o);
    return v;
}
__device__ __forceinline__ float warpMax(float v) {
    #pragma unroll
    for (int o = 16; o; o >>= 1) v = fmaxf(v, __shfl_down_sync(0xffffffffu, v, o));
    return v;
}

// Bitonic compare-exchange via shuffle (j < 32). j < k always, so asc=(idx&k)==0 is
// identical for both partners of a pair.
__device__ __forceinline__ void ceShfl(float& e, int idx, int k, int j) {
    float p = __shfl_xor_sync(0xffffffffu, e, j);
    bool lower = (idx & j) == 0;
    bool asc   = (idx & k) == 0;
    e = (lower == asc) ? fminf(e, p) : fmaxf(e, p);
}
// In-thread j==32 stage: e0 at idx0 (bit5 clear -> lower partner), e1 at idx0+32.
__device__ __forceinline__ void ceLocal(float& e0, float& e1, int idx0, int k) {
    bool asc = (idx0 & k) == 0;
    if ((e0 > e1) == asc) { float tmp = e0; e0 = e1; e1 = tmp; }
}
// Tail stages j=32..1 of merge step k, fully in registers.
__device__ __forceinline__ void warpTail(float& e0, float& e1, int idx0, int idx1, int k) {
    ceLocal(e0, e1, idx0, k);
    #pragma unroll
    for (int j = 16; j > 0; j >>= 1) { ceShfl(e0, idx0, k, j); ceShfl(e1, idx1, k, j); }
}

// ================= Fused kernel: stats + reg-bitonic sort + handshake + search + finalize =====
__global__ __launch_bounds__(NTHR) void kFused(const float* __restrict__ pred_mz,
                                               const float* __restrict__ mz,
                                               const float* __restrict__ intensity,
                                               const float* __restrict__ pred_intensity,
                                               float* __restrict__ out) {
    __shared__ float        sm[SKSZ];      // sort staging (first 512) then 4 skewed regions
    __shared__ float        red7[7][8];
    __shared__ float        redI[8];
    __shared__ unsigned int sflag;

    const int t    = threadIdx.x;
    const int lane = t & 31;
    const int w    = t >> 5;
    const int blk  = blockIdx.x;
    const int b    = blk >> 2;            // batch
    const int segBase = blk * CHUNK;      // blk = b*4 + c -> contiguous global segment

    // Sort-layout ownership: lane L of warp w owns idx0=64w+L, idx1=idx0+32.
    const int idx0 = 64 * w + lane;
    const int idx1 = idx0 + 32;
    const int g0 = segBase + idx0, g1 = segBase + idx1;

    const float a0 = pred_mz[g0],        a1 = pred_mz[g1];
    const float c0 = mz[g0],             c1 = mz[g1];
    const float x0 = intensity[g0],      x1 = intensity[g1];
    const float y0 = pred_intensity[g0], y1 = pred_intensity[g1];

    // ---- per-block stats partials ----
    float cnt = 0.f, dmz2 = 0.f, di2 = 0.f, spmz = 0.f, spint = 0.f, mxm = 0.f, mxi = 0.f;
    {
        float av[2] = {a0, a1}, cv[2] = {c0, c1}, xv[2] = {x0, x1}, yv[2] = {y0, y1};
        #pragma unroll
        for (int r = 0; r < 2; r++) {
            float a = av[r], cc = cv[r], x = xv[r], y = yv[r];
            cnt += (a >= 0.f ? 1.f : 0.f) + (cc >= 0.f ? 1.f : 0.f);
            float d1 = a - cc; dmz2 += d1 * d1;
            float d2 = y - x;  di2  += d2 * d2;
            float sa = (float)((a  > 0.f) - (a  < 0.f));
            float sc = (float)((cc > 0.f) - (cc < 0.f));
            float sx = (float)((x  > 0.f) - (x  < 0.f));
            float sy = (float)((y  > 0.f) - (y  < 0.f));
            spmz  += fabsf(sa - sc);
            spint += fabsf(sy - sx);
            mxm = fmaxf(mxm, fabsf(cc));
            mxi = fmaxf(mxi, fabsf(x));
        }
    }
    cnt = warpSum(cnt); dmz2 = warpSum(dmz2); di2 = warpSum(di2);
    spmz = warpSum(spmz); spint = warpSum(spint);
    mxm = warpMax(mxm); mxi = warpMax(mxi);
    if (lane == 0) {
        red7[0][w] = cnt; red7[1][w] = dmz2; red7[2][w] = di2;
        red7[3][w] = spmz; red7[4][w] = spint; red7[5][w] = mxm; red7[6][w] = mxi;
    }

    // ---- warp-register bitonic sort of each 64-run (k=2..64): zero block barriers ----
    float e0 = (c0 >= 0.f) ? c0 : 0.f;     // masked mz
    float e1 = (c1 >= 0.f) ? c1 : 0.f;
    #pragma unroll
    for (int k = 2; k <= 64; k <<= 1) {
        #pragma unroll
        for (int j = k >> 1; j > 0; j >>= 1) {
            if (j == 32) ceLocal(e0, e1, idx0, k);
            else         { ceShfl(e0, idx0, k, j); ceShfl(e1, idx1, k, j); }
        }
    }

    __syncthreads();                       // covers red7 writes
    if (t < 7) {
        float v = red7[t][0];
        if (t < 5) { for (int i = 1; i < 8; i++) v += red7[t][i]; }
        else       { for (int i = 1; i < 8; i++) v = fmaxf(v, red7[t][i]); }
        switch (t) {
            case 0: g_pcnt[blk] = v; break;
            case 1: g_pdmz[blk] = v; break;
            case 2: g_pdi [blk] = v; break;
            case 3: g_pspm[blk] = v; break;
            case 4: g_pspi[blk] = v; break;
            case 5: g_pmxm[blk] = v; break;
            case 6: g_pmxi[blk] = v; break;
        }
    }

    // ---- merge stages k=128,256,512: only j>=64 passes touch smem ----
    sm[idx0] = e0; sm[idx1] = e1;
    __syncthreads();
    #pragma unroll
    for (int k = 128; k <= CHUNK; k <<= 1) {
        #pragma unroll
        for (int j = k >> 1; j >= 64; j >>= 1) {
            int i  = ((t & ~(j - 1)) << 1) | (t & (j - 1));
            int ii = i + j;
            float va = sm[i], vb = sm[ii];
            bool asc = (i & k) == 0;
            if ((va > vb) == asc) { sm[i] = vb; sm[ii] = va; }
            __syncthreads();
        }
        e0 = sm[idx0]; e1 = sm[idx1];
        warpTail(e0, e1, idx0, idx1, k);
        if (k < CHUNK) {
            sm[idx0] = e0; sm[idx1] = e1;
            __syncthreads();
        }
    }

    // ---- publish sorted chunk from registers; ticket; spin for 3 siblings ----
    g_sorted[segBase + idx0] = e0;
    g_sorted[segBase + idx1] = e1;
    __threadfence();
    __syncthreads();
    if (t == 0) {
        unsigned int v = atomicAdd(&g_arrive[b], 1u) + 1u;
        unsigned int target = (v + 3u) & ~3u;          // ceil to multiple of 4 (replay-safe)
        while (atomicAdd(&g_arrive[b], 0u) < target) __nanosleep(20);
        __threadfence();                                // acquire for g_sorted reads
    }
    __syncthreads();

    // ---- load all 4 sorted chunks of batch b into skewed regions ----
    #pragma unroll
    for (int rc = 0; rc < NCHUNK; rc++) {
        float2 v = __ldcg(((const float2*)g_sorted) + (b * SEQ + rc * CHUNK) / 2 + t);
        int sk = REGZ * rc + SK(2 * t);
        sm[sk] = v.x; sm[sk + 1] = v.y;
    }
    __syncthreads();

    // ---- soft intersect: max_j exp(-|a-mz_j|/T) = exp(-min_dist/T).
    // 8 searches (2 queries x 4 chunks) interleaved step-major: MLP=8.
    float acc = 0.f;
    {
        float av[2] = {a0, a1}, yv[2] = {y0, y1};
        int pos[2][NCHUNK] = {{0,0,0,0},{0,0,0,0}};
        #pragma unroll
        for (int st = CHUNK / 2; st > 0; st >>= 1) {
            #pragma unroll
            for (int q = 0; q < 2; q++) {
                #pragma unroll
                for (int rc = 0; rc < NCHUNK; rc++) {
                    if (sm[REGZ * rc + SK(pos[q][rc] + st - 1)] < av[q])
                        pos[q][rc] += st;               // pos <= 511 always
                }
            }
        }
        #pragma unroll
        for (int q = 0; q < 2; q++) {
            float a = av[q];
            float d = 3.0e38f;
            #pragma unroll
            for (int rc = 0; rc < NCHUNK; rc++) {
                int p = pos[q][rc];
                float hi = sm[REGZ * rc + SK(p)];
                float lo = sm[REGZ * rc + SK(p > 0 ? p - 1 : 0)];
                d = fminf(d, fabsf(a - hi));            // bracket covers pos==0 and
                d = fminf(d, fabsf(a - lo));            // saturated pos==511 via fabsf
            }
            float m = __expf(-10.0f * d) * yv[q];
            acc += (a >= 0.f) ? m : 0.f;                // masked query contributes 0
        }
    }
    acc = warpSum(acc);
    if (lane == 0) redI[w] = acc;
    __syncthreads();
    if (t == 0) {
        float v = redI[0];
        for (int i = 1; i < 8; i++) v += redI[i];
        g_pint[blk] = v;
        __threadfence();
        unsigned int v2 = atomicAdd(&g_done, 1u) + 1u;
        unsigned int target = (v2 + 127u) & ~127u;     // ceil to multiple of 128
        sflag = (v2 == target) ? 1u : 0u;
    }
    __syncthreads();

    // ---- globally-last block finalizes the 4 scalars ----
    if (sflag) {
        __threadfence();                                // acquire partials
        if (t < 32) {
            const float EPS = 1e-8f;
            float I = 0.f, U = 0.f, sdm = 0.f, sdi = 0.f, ssm = 0.f, ssi = 0.f;
            float mm = 0.f, mi = 0.f;
            #pragma unroll
            for (int cc = 0; cc < 4; cc++) {
                int idx = 4 * t + cc;                   // batch = t, its 4 chunk partials
                I   += __ldcg(&g_pint[idx]);
                U   += __ldcg(&g_pcnt[idx]);
                sdm += __ldcg(&g_pdmz[idx]);
                sdi += __ldcg(&g_pdi [idx]);
                ssm += __ldcg(&g_pspm[idx]);
                ssi += __ldcg(&g_pspi[idx]);
                mm = fmaxf(mm, __ldcg(&g_pmxm[idx]));
                mi = fmaxf(mi, __ldcg(&g_pmxi[idx]));
            }
            float sj = 1.f - (I + EPS) / (U + EPS);
            sj  = warpSum(sj);
            sdm = warpSum(sdm); sdi = warpSum(sdi);
            ssm = warpSum(ssm); ssi = warpSum(ssi);
            mm  = warpMax(mm);  mi  = warpMax(mi);
            if (t == 0) {
                const float N = (float)(BATCH * SEQ);
                out[0] = sj / (float)BATCH;             // soft jaccard loss
                out[1] = (sdm / N) / (mm * mm);         // mse mz (normalized)
                out[2] = (sdi / N) / (mi * mi);         // mse intensity (normalized)
                out[3] = (ssm / N + ssi / N) * 0.5f;    // sign penalty
            }
        }
    }
}

extern "C" void kernel_launch(void* const* d_in, const int* in_sizes, int n_in,
                              void* d_out, int out_size) {
    const float* pred_mz        = (const float*)d_in[0];
    const float* mz             = (const float*)d_in[1];
    const float* intensity      = (const float*)d_in[2];
    const float* pred_intensity = (const float*)d_in[3];
    float* out = (float*)d_out;

    kFused<<<NBLK, NTHR>>>(pred_mz, mz, intensity, pred_intensity, out);
}

// round 11
// speedup vs baseline: 1.1940x; 1.1940x over previous
#include <cuda_runtime.h>
#include <cooperative_groups.h>
namespace cg = cooperative_groups;

#define BATCH  32
#define SEQ    2048
#define CHUNK  512
#define NCHUNK 4                  // SEQ / CHUNK = cluster size
#define NBLK   (BATCH * NCHUNK)   // 128
#define NTHR   256

// ---- scratch (allocation-free __device__ globals; ticket monotone across replays) ----
__device__ float        g_pcnt[NBLK], g_pdmz[NBLK], g_pdi[NBLK], g_pspm[NBLK],
                        g_pspi[NBLK], g_pmxm[NBLK], g_pmxi[NBLK], g_pint[NBLK];
__device__ unsigned int g_done;   // global finalize ticket (non-blocking)

__device__ __forceinline__ int SK(int i) { return i + (i >> 5); }  // bank-skew index
#define REGZ  528                 // skewed size of one 512-chunk region
#define SKSZ  (NCHUNK * REGZ)     // 2112 floats

__device__ __forceinline__ float warpSum(float v) {
    #pragma unroll
    for (int o = 16; o; o >>= 1) v += __shfl_down_sync(0xffffffffu, v, o);
    return v;
}
__device__ __forceinline__ float warpMax(float v) {
    #pragma unroll
    for (int o = 16; o; o >>= 1) v = fmaxf(v, __shfl_down_sync(0xffffffffu, v, o));
    return v;
}

// Bitonic compare-exchange via shuffle (j < 32); asc identical for both partners (j < k).
__device__ __forceinline__ void ceShfl(float& e, int idx, int k, int j) {
    float p = __shfl_xor_sync(0xffffffffu, e, j);
    bool lower = (idx & j) == 0;
    bool asc   = (idx & k) == 0;
    e = (lower == asc) ? fminf(e, p) : fmaxf(e, p);
}
__device__ __forceinline__ void ceLocal(float& e0, float& e1, int idx0, int k) {
    bool asc = (idx0 & k) == 0;
    if ((e0 > e1) == asc) { float tmp = e0; e0 = e1; e1 = tmp; }
}
__device__ __forceinline__ void warpTail(float& e0, float& e1, int idx0, int idx1, int k) {
    ceLocal(e0, e1, idx0, k);
    #pragma unroll
    for (int j = 16; j > 0; j >>= 1) { ceShfl(e0, idx0, k, j); ceShfl(e1, idx1, k, j); }
}

// ============ Fused kernel: 4-CTA cluster per batch, DSMEM chunk exchange ============
__global__ __launch_bounds__(NTHR) __cluster_dims__(NCHUNK, 1, 1)
void kFused(const float* __restrict__ pred_mz,
            const float* __restrict__ mz,
            const float* __restrict__ intensity,
            const float* __restrict__ pred_intensity,
            float* __restrict__ out) {
    __shared__ float        own[CHUNK];    // sorted chunk, plain layout (peers read via DSMEM)
    __shared__ float        srch[SKSZ];    // 4 skewed regions for the search
    __shared__ float        red7[7][8];
    __shared__ float        redI[8];
    __shared__ unsigned int sflag;

    cg::cluster_group cluster = cg::this_cluster();

    const int t    = threadIdx.x;
    const int lane = t & 31;
    const int w    = t >> 5;
    const int blk  = blockIdx.x;
    const int c    = blk & 3;             // rank within cluster (cluster packs consecutive blocks)
    const int segBase = blk * CHUNK;

    // Sort-layout ownership: lane L of warp w owns idx0=64w+L, idx1=idx0+32.
    const int idx0 = 64 * w + lane;
    const int idx1 = idx0 + 32;
    const int g0 = segBase + idx0, g1 = segBase + idx1;

    const float a0 = pred_mz[g0],        a1 = pred_mz[g1];
    const float c0 = mz[g0],             c1 = mz[g1];
    const float x0 = intensity[g0],      x1 = intensity[g1];
    const float y0 = pred_intensity[g0], y1 = pred_intensity[g1];

    // ---- per-block stats partials ----
    float cnt = 0.f, dmz2 = 0.f, di2 = 0.f, spmz = 0.f, spint = 0.f, mxm = 0.f, mxi = 0.f;
    {
        float av[2] = {a0, a1}, cv[2] = {c0, c1}, xv[2] = {x0, x1}, yv[2] = {y0, y1};
        #pragma unroll
        for (int r = 0; r < 2; r++) {
            float a = av[r], cc = cv[r], x = xv[r], y = yv[r];
            cnt += (a >= 0.f ? 1.f : 0.f) + (cc >= 0.f ? 1.f : 0.f);
            float d1 = a - cc; dmz2 += d1 * d1;
            float d2 = y - x;  di2  += d2 * d2;
            float sa = (float)((a  > 0.f) - (a  < 0.f));
            float sc = (float)((cc > 0.f) - (cc < 0.f));
            float sx = (float)((x  > 0.f) - (x  < 0.f));
            float sy = (float)((y  > 0.f) - (y  < 0.f));
            spmz  += fabsf(sa - sc);
            spint += fabsf(sy - sx);
            mxm = fmaxf(mxm, fabsf(cc));
            mxi = fmaxf(mxi, fabsf(x));
        }
    }
    cnt = warpSum(cnt); dmz2 = warpSum(dmz2); di2 = warpSum(di2);
    spmz = warpSum(spmz); spint = warpSum(spint);
    mxm = warpMax(mxm); mxi = warpMax(mxi);
    if (lane == 0) {
        red7[0][w] = cnt; red7[1][w] = dmz2; red7[2][w] = di2;
        red7[3][w] = spmz; red7[4][w] = spint; red7[5][w] = mxm; red7[6][w] = mxi;
    }

    // ---- warp-register bitonic sort of each 64-run (k=2..64): no block barriers ----
    float e0 = (c0 >= 0.f) ? c0 : 0.f;     // masked mz
    float e1 = (c1 >= 0.f) ? c1 : 0.f;
    #pragma unroll
    for (int k = 2; k <= 64; k <<= 1) {
        #pragma unroll
        for (int j = k >> 1; j > 0; j >>= 1) {
            if (j == 32) ceLocal(e0, e1, idx0, k);
            else         { ceShfl(e0, idx0, k, j); ceShfl(e1, idx1, k, j); }
        }
    }

    __syncthreads();                       // covers red7 writes
    if (t < 7) {
        float v = red7[t][0];
        if (t < 5) { for (int i = 1; i < 8; i++) v += red7[t][i]; }
        else       { for (int i = 1; i < 8; i++) v = fmaxf(v, red7[t][i]); }
        switch (t) {
            case 0: g_pcnt[blk] = v; break;
            case 1: g_pdmz[blk] = v; break;
            case 2: g_pdi [blk] = v; break;
            case 3: g_pspm[blk] = v; break;
            case 4: g_pspi[blk] = v; break;
            case 5: g_pmxm[blk] = v; break;
            case 6: g_pmxi[blk] = v; break;
        }
    }

    // ---- merge stages k=128,256,512: only j>=64 passes touch smem ----
    own[idx0] = e0; own[idx1] = e1;
    __syncthreads();
    #pragma unroll
    for (int k = 128; k <= CHUNK; k <<= 1) {
        #pragma unroll
        for (int j = k >> 1; j >= 64; j >>= 1) {
            int i  = ((t & ~(j - 1)) << 1) | (t & (j - 1));
            int ii = i + j;
            float va = own[i], vb = own[ii];
            bool asc = (i & k) == 0;
            if ((va > vb) == asc) { own[i] = vb; own[ii] = va; }
            __syncthreads();
        }
        e0 = own[idx0]; e1 = own[idx1];
        warpTail(e0, e1, idx0, idx1, k);
        own[idx0] = e0; own[idx1] = e1;    // keep own[] current (peers will read it)
        if (k < CHUNK) __syncthreads();
    }

    // ---- cluster barrier: all 4 chunks sorted & visible across the cluster ----
    cluster.sync();

    // ---- gather all 4 sorted chunks into skewed regions (own local, 3 via DSMEM) ----
    #pragma unroll
    for (int rc = 0; rc < NCHUNK; rc++) {
        const float* src = (rc == c) ? own : cluster.map_shared_rank(own, rc);
        float v0 = src[2 * t], v1 = src[2 * t + 1];    // coalesced, adjacent
        int sk = REGZ * rc + SK(2 * t);                // SK(2t+1)=SK(2t)+1
        srch[sk] = v0; srch[sk + 1] = v1;
    }
    // second cluster barrier: nobody may exit (freeing smem) while peers still read
    cluster.sync();

    // ---- soft intersect: max_j exp(-|a-mz_j|/T) = exp(-min_dist/T).
    // 8 searches (2 queries x 4 chunks) interleaved step-major: MLP=8.
    float acc = 0.f;
    {
        float av[2] = {a0, a1}, yv[2] = {y0, y1};
        int pos[2][NCHUNK] = {{0,0,0,0},{0,0,0,0}};
        #pragma unroll
        for (int st = CHUNK / 2; st > 0; st >>= 1) {
            #pragma unroll
            for (int q = 0; q < 2; q++) {
                #pragma unroll
                for (int rc = 0; rc < NCHUNK; rc++) {
                    if (srch[REGZ * rc + SK(pos[q][rc] + st - 1)] < av[q])
                        pos[q][rc] += st;               // pos <= 511 always
                }
            }
        }
        #pragma unroll
        for (int q = 0; q < 2; q++) {
            float a = av[q];
            float d = 3.0e38f;
            #pragma unroll
            for (int rc = 0; rc < NCHUNK; rc++) {
                int p = pos[q][rc];
                float hi = srch[REGZ * rc + SK(p)];
                float lo = srch[REGZ * rc + SK(p > 0 ? p - 1 : 0)];
                d = fminf(d, fabsf(a - hi));            // bracket covers pos==0 and
                d = fminf(d, fabsf(a - lo));            // saturated pos==511 via fabsf
            }
            float m = __expf(-10.0f * d) * yv[q];
            acc += (a >= 0.f) ? m : 0.f;                // masked query contributes 0
        }
    }
    acc = warpSum(acc);
    if (lane == 0) redI[w] = acc;
    __syncthreads();
    if (t == 0) {
        float v = redI[0];
        for (int i = 1; i < 8; i++) v += redI[i];
        g_pint[blk] = v;
        __threadfence();
        unsigned int v2 = atomicAdd(&g_done, 1u) + 1u;  // non-blocking ticket
        unsigned int target = (v2 + 127u) & ~127u;      // ceil to multiple of 128 (replay-safe)
        sflag = (v2 == target) ? 1u : 0u;
    }
    __syncthreads();

    // ---- globally-last block finalizes the 4 scalars ----
    if (sflag) {
        __threadfence();                                // acquire partials
        if (t < 32) {
            const float EPS = 1e-8f;
            float I = 0.f, U = 0.f, sdm = 0.f, sdi = 0.f, ssm = 0.f, ssi = 0.f;
            float mm = 0.f, mi = 0.f;
            #pragma unroll
            for (int cc = 0; cc < 4; cc++) {
                int idx = 4 * t + cc;                   // batch = t, its 4 chunk partials
                I   += __ldcg(&g_pint[idx]);
                U   += __ldcg(&g_pcnt[idx]);
                sdm += __ldcg(&g_pdmz[idx]);
                sdi += __ldcg(&g_pdi [idx]);
                ssm += __ldcg(&g_pspm[idx]);
                ssi += __ldcg(&g_pspi[idx]);
                mm = fmaxf(mm, __ldcg(&g_pmxm[idx]));
                mi = fmaxf(mi, __ldcg(&g_pmxi[idx]));
            }
            float sj = 1.f - (I + EPS) / (U + EPS);
            sj  = warpSum(sj);
            sdm = warpSum(sdm); sdi = warpSum(sdi);
            ssm = warpSum(ssm); ssi = warpSum(ssi);
            mm  = warpMax(mm);  mi  = warpMax(mi);
            if (t == 0) {
                const float N = (float)(BATCH * SEQ);
                out[0] = sj / (float)BATCH;             // soft jaccard loss
                out[1] = (sdm / N) / (mm * mm);         // mse mz (normalized)
                out[2] = (sdi / N) / (mi * mi);         // mse intensity (normalized)
                out[3] = (ssm / N + ssi / N) * 0.5f;    // sign penalty
            }
        }
    }
}

extern "C" void kernel_launch(void* const* d_in, const int* in_sizes, int n_in,
                              void* d_out, int out_size) {
    const float* pred_mz        = (const float*)d_in[0];
    const float* mz             = (const float*)d_in[1];
    const float* intensity      = (const float*)d_in[2];
    const float* pred_intensity = (const float*)d_in[3];
    float* out = (float*)d_out;

    kFused<<<NBLK, NTHR>>>(pred_mz, mz, intensity, pred_intensity, out);
}